// round 3
// baseline (speedup 1.0000x reference)
#include <cuda_runtime.h>
#include <math.h>

// Problem constants
#define N_ROWS 16384     // 4 * 16*16*16 query vectors
#define NE     8192      // codebook entries
#define EDIM   256       // embedding dim
#define SPB    4096      // spatial positions per batch (16*16*16)
#define NTILES 256       // N_ROWS / 64 row tiles

// GEMM tiling
#define KC     16        // K chunk
#define BPAD   132       // padded B tile row (128 codes + 4 pad floats)
#define SMEM_BYTES (256*64*4 + 2*KC*BPAD*4)   // Az + double-buffered Bs = 82432

__device__ float g_w2[NE];
__device__ int   g_counts[NE];
__device__ int   g_idx[N_ROWS];
__device__ float g_lossPart[NTILES];

// ---------------------------------------------------------------------------
// k0: per-code squared norms + zero histogram. One warp per code row.
// ---------------------------------------------------------------------------
__global__ void prep_kernel(const float* __restrict__ w) {
    int gt   = blockIdx.x * blockDim.x + threadIdx.x;
    int warp = gt >> 5;
    int lane = gt & 31;
    if (warp >= NE) return;
    const float* row = w + (size_t)warp * EDIM;
    float s = 0.f;
    #pragma unroll
    for (int k = lane; k < EDIM; k += 32) { float v = row[k]; s = fmaf(v, v, s); }
    #pragma unroll
    for (int o = 16; o > 0; o >>= 1) s += __shfl_xor_sync(0xffffffffu, s, o);
    if (lane == 0) { g_w2[warp] = s; g_counts[warp] = 0; }
}

// ---------------------------------------------------------------------------
// k1: fused distance-GEMM + argmin.
// CTA = 64 rows (one b, 64 consecutive s). Loops over 64 code tiles of 128.
// z tile (64 rows x 256 dims, K-major) persists in SMEM; weight chunks are
// double-buffered. Thread tile: 4 rows x 8 codes (split 4+4 across tile halves
// for conflict-free float4 LDS).
// ---------------------------------------------------------------------------
__global__ void __launch_bounds__(256, 2) argmin_kernel(
    const float* __restrict__ z, const float* __restrict__ w,
    float* __restrict__ outIdxF)
{
    extern __shared__ float smem[];
    float* Az = smem;                 // [256][64] K-major z tile
    float* Bs = smem + 256 * 64;      // [2][KC][BPAD] weight chunks (K-major)

    const int t  = threadIdx.x;
    const int tx = t & 15;            // code group
    const int ty = t >> 4;            // row group
    const int tile = blockIdx.x;
    const int b  = tile >> 6;         // 64 row-tiles per batch
    const int s0 = (tile & 63) << 6;

    const float* zb = z + (size_t)b * (EDIM * SPB) + s0;

    // Load full A tile: Az[k][r] = z[(b*256+k)*4096 + s0 + r]
    #pragma unroll
    for (int rep = 0; rep < 16; rep++) {
        int lin = rep * 256 + t;
        int k   = lin >> 4;
        int r4  = (lin & 15) << 2;
        float4 v = *(const float4*)(zb + (size_t)k * SPB + r4);
        *(float4*)(Az + k * 64 + r4) = v;
    }

    float minv[4]; int mini[4];
    #pragma unroll
    for (int i = 0; i < 4; i++) { minv[i] = 3.4e38f; mini[i] = 0; }

    // B chunk load mapping (per rep): lin = rep*256+t; c = lin>>2; kq = lin&3
    float4 breg[2];
    // Prologue: load chunk 0 of code tile 0 into buffer 0
    #pragma unroll
    for (int rep = 0; rep < 2; rep++) {
        int lin = rep * 256 + t; int c = lin >> 2; int kq = lin & 3;
        breg[rep] = *(const float4*)(w + (size_t)c * EDIM + (kq << 2));
    }
    __syncthreads();   // Az ready too
    #pragma unroll
    for (int rep = 0; rep < 2; rep++) {
        int lin = rep * 256 + t; int c = lin >> 2; int kq = lin & 3;
        Bs[(kq * 4 + 0) * BPAD + c] = breg[rep].x;
        Bs[(kq * 4 + 1) * BPAD + c] = breg[rep].y;
        Bs[(kq * 4 + 2) * BPAD + c] = breg[rep].z;
        Bs[(kq * 4 + 3) * BPAD + c] = breg[rep].w;
    }
    __syncthreads();

    for (int tileC = 0; tileC < 64; tileC++) {
        float acc[4][8];
        #pragma unroll
        for (int i = 0; i < 4; i++)
            #pragma unroll
            for (int j = 0; j < 8; j++) acc[i][j] = 0.f;

        for (int chunk = 0; chunk < 16; chunk++) {
            int buf = chunk & 1;
            int nChunk = chunk + 1, nTile = tileC;
            if (nChunk == 16) { nChunk = 0; nTile++; }
            bool hasNext = (nTile < 64);

            if (hasNext) {   // prefetch next chunk into regs (hidden by compute)
                int nc0 = nTile << 7;
                int nkk = nChunk * KC;
                #pragma unroll
                for (int rep = 0; rep < 2; rep++) {
                    int lin = rep * 256 + t; int c = lin >> 2; int kq = lin & 3;
                    breg[rep] = *(const float4*)(w + (size_t)(nc0 + c) * EDIM + nkk + (kq << 2));
                }
            }

            const float* Bp = Bs + buf * (KC * BPAD);
            const float* Ap = Az + chunk * (KC * 64);
            #pragma unroll
            for (int k = 0; k < KC; k++) {
                float4 av  = *(const float4*)(Ap + k * 64 + (ty << 2));
                float4 bv0 = *(const float4*)(Bp + k * BPAD + (tx << 2));
                float4 bv1 = *(const float4*)(Bp + k * BPAD + 64 + (tx << 2));
                float a[4]  = { av.x, av.y, av.z, av.w };
                float bb[8] = { bv0.x, bv0.y, bv0.z, bv0.w,
                                bv1.x, bv1.y, bv1.z, bv1.w };
                #pragma unroll
                for (int i = 0; i < 4; i++)
                    #pragma unroll
                    for (int j = 0; j < 8; j++)
                        acc[i][j] = fmaf(a[i], bb[j], acc[i][j]);
            }

            if (hasNext) {
                float* Bn = Bs + (buf ^ 1) * (KC * BPAD);
                #pragma unroll
                for (int rep = 0; rep < 2; rep++) {
                    int lin = rep * 256 + t; int c = lin >> 2; int kq = lin & 3;
                    Bn[(kq * 4 + 0) * BPAD + c] = breg[rep].x;
                    Bn[(kq * 4 + 1) * BPAD + c] = breg[rep].y;
                    Bn[(kq * 4 + 2) * BPAD + c] = breg[rep].z;
                    Bn[(kq * 4 + 3) * BPAD + c] = breg[rep].w;
                }
            }
            __syncthreads();
        }

        // Epilogue: d = w2 - 2*dot; update running min (ascending code order
        // within each thread -> strict < keeps first occurrence on ties)
        #pragma unroll
        for (int jh = 0; jh < 2; jh++)
            #pragma unroll
            for (int j = 0; j < 4; j++) {
                int c = (tileC << 7) + jh * 64 + (tx << 2) + j;
                float w2c = __ldg(&g_w2[c]);
                #pragma unroll
                for (int i = 0; i < 4; i++) {
                    float d = fmaf(-2.f, acc[i][jh * 4 + j], w2c);
                    if (d < minv[i]) { minv[i] = d; mini[i] = c; }
                }
            }
    }

    // Cross-thread reduction per row (16 tx lanes cover disjoint code sets).
    __syncthreads();
    float* redv = smem;                       // reuse Az region: 64*16 floats
    int*   redi = (int*)(smem + 64 * 16);     // + 64*16 ints
    #pragma unroll
    for (int i = 0; i < 4; i++) {
        redv[(ty * 4 + i) * 16 + tx] = minv[i];
        redi[(ty * 4 + i) * 16 + tx] = mini[i];
    }
    __syncthreads();
    if (t < 64) {
        float bv = redv[t * 16]; int bi = redi[t * 16];
        #pragma unroll
        for (int q = 1; q < 16; q++) {
            float v = redv[t * 16 + q]; int ii = redi[t * 16 + q];
            if (v < bv || (v == bv && ii < bi)) { bv = v; bi = ii; }
        }
        int n = b * SPB + s0 + t;
        g_idx[n]  = bi;
        outIdxF[n] = (float)bi;
        atomicAdd(&g_counts[bi], 1);
    }
}

// ---------------------------------------------------------------------------
// k2: codebook gather -> z_q output (straight-through value) + loss partials.
// CTA = 64 s positions (fixed b), all 256 channels. Coalesced z reads/writes;
// weight gathers hit L2 (8 MB resident).
// ---------------------------------------------------------------------------
__global__ void gather_kernel(const float* __restrict__ z,
                              const float* __restrict__ w,
                              float* __restrict__ out)
{
    __shared__ int   sIdx[64];
    __shared__ float red[256];
    int t = threadIdx.x;
    int tile = blockIdx.x;
    int b  = tile >> 6;
    int s0 = (tile & 63) << 6;
    if (t < 64) sIdx[t] = g_idx[b * SPB + s0 + t];
    __syncthreads();

    int sL = t & 63, cg = t >> 6;
    size_t base = (size_t)b * (EDIM * SPB) + s0 + sL;
    const float* wrow = w + (size_t)sIdx[sL] * EDIM;
    float acc = 0.f;
    for (int c = cg; c < EDIM; c += 4) {
        float wq = __ldg(&wrow[c]);
        float zv = z[base + (size_t)c * SPB];
        out[base + (size_t)c * SPB] = zv + (wq - zv);  // straight-through value
        float df = wq - zv;                            // (z_q.detach - z)
        acc = fmaf(df, df, acc);
    }
    red[t] = acc;
    __syncthreads();
    for (int o = 128; o > 0; o >>= 1) {
        if (t < o) red[t] += red[t + o];
        __syncthreads();
    }
    if (t == 0) g_lossPart[tile] = red[0];
}

// ---------------------------------------------------------------------------
// k3: scalars — loss, perplexity, unique.
// ---------------------------------------------------------------------------
__global__ void finalize_kernel(float* __restrict__ outScal) {
    __shared__ float sp[256];
    __shared__ float sl[256];
    __shared__ int   su[256];
    int t = threadIdx.x;
    float pl = 0.f; int un = 0;
    for (int e = t; e < NE; e += 256) {
        int cnt = g_counts[e];
        if (cnt > 0) {
            un++;
            float p = (float)cnt * (1.f / 16384.f);
            pl = fmaf(p, logf(p + 1e-10f), pl);
        }
    }
    sp[t] = pl; su[t] = un; sl[t] = g_lossPart[t];
    __syncthreads();
    for (int o = 128; o > 0; o >>= 1) {
        if (t < o) { sp[t] += sp[t + o]; su[t] += su[t + o]; sl[t] += sl[t + o]; }
        __syncthreads();
    }
    if (t == 0) {
        outScal[0] = 0.25f * sl[0] * (1.f / 4194304.f);  // BETA * mean
        outScal[1] = expf(-sp[0]);                       // perplexity
        outScal[2] = (float)su[0];                       // unique
    }
}

// ---------------------------------------------------------------------------
extern "C" void kernel_launch(void* const* d_in, const int* in_sizes, int n_in,
                              void* d_out, int out_size)
{
    const float* z = (const float*)d_in[0];   // [4,256,16,16,16]
    const float* w = (const float*)d_in[1];   // [8192,256]
    float* out = (float*)d_out;

    // Layout: [z_q (4194304) | loss | perplexity | unique | idx (16384)]
    int idxOff = out_size - N_ROWS;

    cudaFuncSetAttribute(argmin_kernel,
                         cudaFuncAttributeMaxDynamicSharedMemorySize, SMEM_BYTES);

    prep_kernel<<<NE * 32 / 256, 256>>>(w);
    argmin_kernel<<<NTILES, 256, SMEM_BYTES>>>(z, w, out + idxOff);
    gather_kernel<<<NTILES, 256>>>(z, w, out);
    finalize_kernel<<<1, 256>>>(out + idxOff - 3);
}

// round 4
// speedup vs baseline: 1.0052x; 1.0052x over previous
#include <cuda_runtime.h>
#include <math.h>

// Problem constants
#define N_ROWS 16384     // 4 * 16*16*16 query vectors
#define NE     8192      // codebook entries
#define EDIM   256       // embedding dim
#define SPB    4096      // spatial positions per batch (16*16*16)
#define NTILES 256       // N_ROWS / 64 row tiles

// GEMM tiling
#define KC     16        // K chunk
#define BPAD   132       // padded B tile row (128 codes + 4 pad floats)
#define SMEM_BYTES (256*64*4 + 2*KC*BPAD*4)   // Az + double-buffered Bs = 82432

__device__ float g_w2[NE];
__device__ int   g_counts[NE];
__device__ int   g_idx[N_ROWS];
__device__ float g_lossPart[NTILES];

// ---- packed fp32 helpers (Blackwell f32x2: 2x fp32 FMA throughput) --------
__device__ __forceinline__ unsigned long long pack2(float lo, float hi) {
    unsigned long long r;
    asm("mov.b64 %0, {%1, %2};" : "=l"(r) : "f"(lo), "f"(hi));
    return r;
}
__device__ __forceinline__ void unpack2(unsigned long long v, float& lo, float& hi) {
    asm("mov.b64 {%0, %1}, %2;" : "=f"(lo), "=f"(hi) : "l"(v));
}
__device__ __forceinline__ void ffma2(unsigned long long& d,
                                      unsigned long long a,
                                      unsigned long long b) {
    asm("fma.rn.f32x2 %0, %1, %2, %0;" : "+l"(d) : "l"(a), "l"(b));
}

// ---------------------------------------------------------------------------
// k0: per-code squared norms + zero histogram. One warp per code row.
// ---------------------------------------------------------------------------
__global__ void prep_kernel(const float* __restrict__ w) {
    int gt   = blockIdx.x * blockDim.x + threadIdx.x;
    int warp = gt >> 5;
    int lane = gt & 31;
    if (warp >= NE) return;
    const float* row = w + (size_t)warp * EDIM;
    float s = 0.f;
    #pragma unroll
    for (int k = lane; k < EDIM; k += 32) { float v = row[k]; s = fmaf(v, v, s); }
    #pragma unroll
    for (int o = 16; o > 0; o >>= 1) s += __shfl_xor_sync(0xffffffffu, s, o);
    if (lane == 0) { g_w2[warp] = s; g_counts[warp] = 0; }
}

// ---------------------------------------------------------------------------
// k1: fused distance-GEMM + argmin, packed-f32x2 inner loop.
// CTA = 64 rows (one b, 64 consecutive s). Loops over 64 code tiles of 128.
// z tile (64 rows x 256 dims, K-major) persists in SMEM; weight chunks are
// double-buffered. Thread tile: 4 rows x 8 codes; the 8 codes are held as
// 4 packed f32x2 accumulators per row (pairs of adjacent codes).
// ---------------------------------------------------------------------------
__global__ void __launch_bounds__(256, 2) argmin_kernel(
    const float* __restrict__ z, const float* __restrict__ w,
    float* __restrict__ outIdxF)
{
    extern __shared__ float smem[];
    float* Az = smem;                 // [256][64] K-major z tile
    float* Bs = smem + 256 * 64;      // [2][KC][BPAD] weight chunks (K-major)

    const int t  = threadIdx.x;
    const int tx = t & 15;            // code group
    const int ty = t >> 4;            // row group
    const int tile = blockIdx.x;
    const int b  = tile >> 6;         // 64 row-tiles per batch
    const int s0 = (tile & 63) << 6;

    const float* zb = z + (size_t)b * (EDIM * SPB) + s0;

    // Load full A tile: Az[k][r] = z[(b*256+k)*4096 + s0 + r]
    #pragma unroll
    for (int rep = 0; rep < 16; rep++) {
        int lin = rep * 256 + t;
        int k   = lin >> 4;
        int r4  = (lin & 15) << 2;
        float4 v = *(const float4*)(zb + (size_t)k * SPB + r4);
        *(float4*)(Az + k * 64 + r4) = v;
    }

    float minv[4]; int mini[4];
    #pragma unroll
    for (int i = 0; i < 4; i++) { minv[i] = 3.4e38f; mini[i] = 0; }

    // B chunk load mapping (per rep): lin = rep*256+t; c = lin>>2; kq = lin&3
    float4 breg[2];
    // Prologue: load chunk 0 of code tile 0 into buffer 0
    #pragma unroll
    for (int rep = 0; rep < 2; rep++) {
        int lin = rep * 256 + t; int c = lin >> 2; int kq = lin & 3;
        breg[rep] = *(const float4*)(w + (size_t)c * EDIM + (kq << 2));
    }
    __syncthreads();   // Az ready too
    #pragma unroll
    for (int rep = 0; rep < 2; rep++) {
        int lin = rep * 256 + t; int c = lin >> 2; int kq = lin & 3;
        Bs[(kq * 4 + 0) * BPAD + c] = breg[rep].x;
        Bs[(kq * 4 + 1) * BPAD + c] = breg[rep].y;
        Bs[(kq * 4 + 2) * BPAD + c] = breg[rep].z;
        Bs[(kq * 4 + 3) * BPAD + c] = breg[rep].w;
    }
    __syncthreads();

    for (int tileC = 0; tileC < 64; tileC++) {
        // acc2[i][jp]: row i, code-pair jp. jp 0..1 -> codes tx*4+{0..3};
        // jp 2..3 -> codes 64+tx*4+{0..3}. Lo half = even code, hi = odd.
        unsigned long long acc2[4][4];
        #pragma unroll
        for (int i = 0; i < 4; i++)
            #pragma unroll
            for (int jp = 0; jp < 4; jp++) acc2[i][jp] = 0ull;

        for (int chunk = 0; chunk < 16; chunk++) {
            int buf = chunk & 1;
            int nChunk = chunk + 1, nTile = tileC;
            if (nChunk == 16) { nChunk = 0; nTile++; }
            bool hasNext = (nTile < 64);

            if (hasNext) {   // prefetch next chunk into regs (hidden by compute)
                int nc0 = nTile << 7;
                int nkk = nChunk * KC;
                #pragma unroll
                for (int rep = 0; rep < 2; rep++) {
                    int lin = rep * 256 + t; int c = lin >> 2; int kq = lin & 3;
                    breg[rep] = *(const float4*)(w + (size_t)(nc0 + c) * EDIM + nkk + (kq << 2));
                }
            }

            const float* Bp = Bs + buf * (KC * BPAD);
            const float* Ap = Az + chunk * (KC * 64);
            #pragma unroll
            for (int k = 0; k < KC; k++) {
                float4 av  = *(const float4*)(Ap + k * 64 + (ty << 2));
                float4 bv0 = *(const float4*)(Bp + k * BPAD + (tx << 2));
                float4 bv1 = *(const float4*)(Bp + k * BPAD + 64 + (tx << 2));
                // B pairs: adjacent floats of the float4 quads (aligned reg pairs)
                unsigned long long b2[4];
                b2[0] = pack2(bv0.x, bv0.y);
                b2[1] = pack2(bv0.z, bv0.w);
                b2[2] = pack2(bv1.x, bv1.y);
                b2[3] = pack2(bv1.z, bv1.w);
                float a[4] = { av.x, av.y, av.z, av.w };
                #pragma unroll
                for (int i = 0; i < 4; i++) {
                    unsigned long long a2 = pack2(a[i], a[i]);
                    #pragma unroll
                    for (int jp = 0; jp < 4; jp++)
                        ffma2(acc2[i][jp], a2, b2[jp]);
                }
            }

            if (hasNext) {
                float* Bn = Bs + (buf ^ 1) * (KC * BPAD);
                #pragma unroll
                for (int rep = 0; rep < 2; rep++) {
                    int lin = rep * 256 + t; int c = lin >> 2; int kq = lin & 3;
                    Bn[(kq * 4 + 0) * BPAD + c] = breg[rep].x;
                    Bn[(kq * 4 + 1) * BPAD + c] = breg[rep].y;
                    Bn[(kq * 4 + 2) * BPAD + c] = breg[rep].z;
                    Bn[(kq * 4 + 3) * BPAD + c] = breg[rep].w;
                }
            }
            __syncthreads();
        }

        // Epilogue: d = w2 - 2*dot; update running min (ascending code order
        // within each thread -> strict < keeps first occurrence on ties)
        #pragma unroll
        for (int jh = 0; jh < 2; jh++)
            #pragma unroll
            for (int jq = 0; jq < 2; jq++) {
                int jp = jh * 2 + jq;
                int cbase = (tileC << 7) + jh * 64 + (tx << 2) + jq * 2;
                float w2a = __ldg(&g_w2[cbase]);
                float w2b = __ldg(&g_w2[cbase + 1]);
                #pragma unroll
                for (int i = 0; i < 4; i++) {
                    float dotA, dotB;
                    unpack2(acc2[i][jp], dotA, dotB);
                    float dA = fmaf(-2.f, dotA, w2a);
                    float dB = fmaf(-2.f, dotB, w2b);
                    if (dA < minv[i]) { minv[i] = dA; mini[i] = cbase; }
                    if (dB < minv[i]) { minv[i] = dB; mini[i] = cbase + 1; }
                }
            }
    }

    // Cross-thread reduction per row (16 tx lanes cover disjoint code sets).
    __syncthreads();
    float* redv = smem;                       // reuse Az region: 64*16 floats
    int*   redi = (int*)(smem + 64 * 16);     // + 64*16 ints
    #pragma unroll
    for (int i = 0; i < 4; i++) {
        redv[(ty * 4 + i) * 16 + tx] = minv[i];
        redi[(ty * 4 + i) * 16 + tx] = mini[i];
    }
    __syncthreads();
    if (t < 64) {
        float bv = redv[t * 16]; int bi = redi[t * 16];
        #pragma unroll
        for (int q = 1; q < 16; q++) {
            float v = redv[t * 16 + q]; int ii = redi[t * 16 + q];
            if (v < bv || (v == bv && ii < bi)) { bv = v; bi = ii; }
        }
        int n = b * SPB + s0 + t;
        g_idx[n]  = bi;
        outIdxF[n] = (float)bi;
        atomicAdd(&g_counts[bi], 1);
    }
}

// ---------------------------------------------------------------------------
// k2: codebook gather -> z_q output (straight-through value) + loss partials.
// ---------------------------------------------------------------------------
__global__ void gather_kernel(const float* __restrict__ z,
                              const float* __restrict__ w,
                              float* __restrict__ out)
{
    __shared__ int   sIdx[64];
    __shared__ float red[256];
    int t = threadIdx.x;
    int tile = blockIdx.x;
    int b  = tile >> 6;
    int s0 = (tile & 63) << 6;
    if (t < 64) sIdx[t] = g_idx[b * SPB + s0 + t];
    __syncthreads();

    int sL = t & 63, cg = t >> 6;
    size_t base = (size_t)b * (EDIM * SPB) + s0 + sL;
    const float* wrow = w + (size_t)sIdx[sL] * EDIM;
    float acc = 0.f;
    for (int c = cg; c < EDIM; c += 4) {
        float wq = __ldg(&wrow[c]);
        float zv = z[base + (size_t)c * SPB];
        out[base + (size_t)c * SPB] = zv + (wq - zv);  // straight-through value
        float df = wq - zv;                            // (z_q.detach - z)
        acc = fmaf(df, df, acc);
    }
    red[t] = acc;
    __syncthreads();
    for (int o = 128; o > 0; o >>= 1) {
        if (t < o) red[t] += red[t + o];
        __syncthreads();
    }
    if (t == 0) g_lossPart[tile] = red[0];
}

// ---------------------------------------------------------------------------
// k3: scalars — loss, perplexity, unique.
// ---------------------------------------------------------------------------
__global__ void finalize_kernel(float* __restrict__ outScal) {
    __shared__ float sp[256];
    __shared__ float sl[256];
    __shared__ int   su[256];
    int t = threadIdx.x;
    float pl = 0.f; int un = 0;
    for (int e = t; e < NE; e += 256) {
        int cnt = g_counts[e];
        if (cnt > 0) {
            un++;
            float p = (float)cnt * (1.f / 16384.f);
            pl = fmaf(p, logf(p + 1e-10f), pl);
        }
    }
    sp[t] = pl; su[t] = un; sl[t] = g_lossPart[t];
    __syncthreads();
    for (int o = 128; o > 0; o >>= 1) {
        if (t < o) { sp[t] += sp[t + o]; su[t] += su[t + o]; sl[t] += sl[t + o]; }
        __syncthreads();
    }
    if (t == 0) {
        outScal[0] = 0.25f * sl[0] * (1.f / 4194304.f);  // BETA * mean
        outScal[1] = expf(-sp[0]);                       // perplexity
        outScal[2] = (float)su[0];                       // unique
    }
}

// ---------------------------------------------------------------------------
extern "C" void kernel_launch(void* const* d_in, const int* in_sizes, int n_in,
                              void* d_out, int out_size)
{
    const float* z = (const float*)d_in[0];   // [4,256,16,16,16]
    const float* w = (const float*)d_in[1];   // [8192,256]
    float* out = (float*)d_out;

    // Layout: [z_q (4194304) | loss | perplexity | unique | idx (16384)]
    int idxOff = out_size - N_ROWS;

    cudaFuncSetAttribute(argmin_kernel,
                         cudaFuncAttributeMaxDynamicSharedMemorySize, SMEM_BYTES);

    prep_kernel<<<NE * 32 / 256, 256>>>(w);
    argmin_kernel<<<NTILES, 256, SMEM_BYTES>>>(z, w, out + idxOff);
    gather_kernel<<<NTILES, 256>>>(z, w, out);
    finalize_kernel<<<1, 256>>>(out + idxOff - 3);
}

// round 8
// speedup vs baseline: 1.9033x; 1.8935x over previous
#include <cuda_runtime.h>
#include <cuda_bf16.h>
#include <math.h>
#include <stdint.h>

#define N_ROWS 16384
#define NE     8192
#define EDIM   256
#define SPB    4096
#define MARGIN 6e-3f

#define NTILE    128                  // codes per tile
#define NT_TILES 64                   // NE / NTILE
#define KCH      64                   // k per B chunk
#define GLOBS    256                  // NT_TILES * 4 chunks

#define A_LO_OFF   65536
#define B_BASE     131072
#define B_BUF_SZ   36864              // hi(128*144) + lo(128*144)
#define B_LO_OFF   18432
#define B_STRIDE   144                // 64 bf16 = 128B + 16B pad
#define SM_TOTAL   204800             // 131072 + 2*36864

__device__ float         g_w2[NE];
__device__ int           g_counts[NE];
__device__ int           g_idx[N_ROWS];
__device__ float         g_lossPart[256];
__device__ __nv_bfloat16 g_wh[NE * EDIM];
__device__ __nv_bfloat16 g_wl[NE * EDIM];
__device__ int           g_flagCnt;
__device__ int           g_flagList[N_ROWS];

// mma.sync m16n8k16 bf16 (arch-portable: compiles for compute_103)
__device__ __forceinline__ void mma_bf16(float* c, const uint4& a,
                                         uint32_t b0, uint32_t b1) {
    asm volatile(
        "mma.sync.aligned.m16n8k16.row.col.f32.bf16.bf16.f32 "
        "{%0,%1,%2,%3}, {%4,%5,%6,%7}, {%8,%9}, {%0,%1,%2,%3};"
        : "+f"(c[0]), "+f"(c[1]), "+f"(c[2]), "+f"(c[3])
        : "r"(a.x), "r"(a.y), "r"(a.z), "r"(a.w), "r"(b0), "r"(b1));
}

// ---- k0: w norms, bf16 hi/lo split, zero counts/flags ---------------------
__global__ void prep_kernel(const float* __restrict__ w) {
    int gt = blockIdx.x * blockDim.x + threadIdx.x;
    if (gt == 0) g_flagCnt = 0;
    int code = gt >> 5, lane = gt & 31;
    if (code >= NE) return;
    const float* row = w + (size_t)code * EDIM;
    float s = 0.f;
    #pragma unroll
    for (int i = 0; i < 8; i++) {
        int k = lane * 8 + i;
        float v = row[k];
        s = fmaf(v, v, s);
        __nv_bfloat16 h = __float2bfloat16(v);
        __nv_bfloat16 l = __float2bfloat16(v - __bfloat162float(h));
        g_wh[code * EDIM + k] = h;
        g_wl[code * EDIM + k] = l;
    }
    #pragma unroll
    for (int o = 16; o > 0; o >>= 1) s += __shfl_xor_sync(0xffffffffu, s, o);
    if (lane == 0) { g_w2[code] = s; g_counts[code] = 0; }
}

// ---- B chunk staging ------------------------------------------------------
__device__ __forceinline__ void ldgB(int g, int tid, uint4* hv, uint4* lv) {
    int n0 = (g >> 2) * NTILE, k0 = (g & 3) * KCH;
    #pragma unroll
    for (int p = 0; p < 4; p++) {
        int lin = p * 256 + tid;
        int n = lin >> 3, j = lin & 7;
        size_t off = (size_t)(n0 + n) * EDIM + k0 + j * 8;
        hv[p] = *(const uint4*)(g_wh + off);
        lv[p] = *(const uint4*)(g_wl + off);
    }
}
__device__ __forceinline__ void stsB(char* smem, int g, int tid,
                                     const uint4* hv, const uint4* lv) {
    char* bb = smem + B_BASE + (g & 1) * B_BUF_SZ;
    #pragma unroll
    for (int p = 0; p < 4; p++) {
        int lin = p * 256 + tid;
        int n = lin >> 3, j = lin & 7;
        *(uint4*)(bb + n * B_STRIDE + j * 16) = hv[p];
        *(uint4*)(bb + B_LO_OFF + n * B_STRIDE + j * 16) = lv[p];
    }
}

// merge two (m1,m2,i1) triples; tie forces m2=m1 -> gap 0 -> flagged
#define MERGE(m1v, m2v, i1v, o1, o2, oi) do {                      \
    if ((o1) < (m1v)) { (m2v) = fminf((m1v), (o2)); (m1v) = (o1); (i1v) = (oi); } \
    else if ((o1) > (m1v)) { (m2v) = fminf((m2v), (o1)); }         \
    else { (i1v) = min((i1v), (oi)); (m2v) = (m1v); }              \
} while (0)

// ---- k1: HMMA distance GEMM + certified argmin ----------------------------
__global__ void __launch_bounds__(256, 1) argmin_hmma_kernel(
    const float* __restrict__ z, float* __restrict__ outIdxF)
{
    extern __shared__ char smem[];
    const int tid = threadIdx.x;
    const int wid = tid >> 5, lane = tid & 31;
    const int wm = wid & 3, wn = wid >> 2;       // row group (32), col group (64)

    // ---- B(0) prefetch first to overlap with A staging
    uint4 hv[4], lv[4];
    ldgB(0, tid, hv, lv);

    // ---- A staging: z rows -> bf16 hi/lo, fragment-permuted layout --------
    // A_s layout: [mb(8)][kstep(16)] blocks of 512B; within block lane*16 holds
    // uint4 slots {(r,2q),(r+8,2q),(r,2q+8),(r+8,2q+8)} (bf16x2 per u32).
    {
        int b = blockIdx.x >> 5, s0 = (blockIdx.x & 31) << 7;
        const float* zb = z + (size_t)b * (EDIM * SPB) + s0;
        #pragma unroll
        for (int it = 0; it < 16; it++) {
            int lin = it * 256 + tid;
            int kp = lin >> 5, m4 = lin & 31;
            float4 va = *(const float4*)(zb + (size_t)(2 * kp) * SPB + 4 * m4);
            float4 vb = *(const float4*)(zb + (size_t)(2 * kp + 1) * SPB + 4 * m4);
            int s = kp >> 3, w8 = kp & 7, kh = w8 >> 2, q = w8 & 3;
            float A0[4] = { va.x, va.y, va.z, va.w };
            float B0[4] = { vb.x, vb.y, vb.z, vb.w };
            #pragma unroll
            for (int j = 0; j < 4; j++) {
                int m = m4 * 4 + j;
                int mb = m >> 4, mr = m & 15, r = mr & 7, mh = mr >> 3;
                int slot = mh + 2 * kh;
                uint32_t off = (uint32_t)(((mb * 16 + s) * 8 + r) * 64 + q * 16 + slot * 4);
                __nv_bfloat16 h0 = __float2bfloat16(A0[j]);
                __nv_bfloat16 h1 = __float2bfloat16(B0[j]);
                __nv_bfloat16 l0 = __float2bfloat16(A0[j] - __bfloat162float(h0));
                __nv_bfloat16 l1 = __float2bfloat16(B0[j] - __bfloat162float(h1));
                *(uint32_t*)(smem + off) =
                    (uint32_t)__bfloat16_as_ushort(h0) | ((uint32_t)__bfloat16_as_ushort(h1) << 16);
                *(uint32_t*)(smem + A_LO_OFF + off) =
                    (uint32_t)__bfloat16_as_ushort(l0) | ((uint32_t)__bfloat16_as_ushort(l1) << 16);
            }
        }
    }
    stsB(smem, 0, tid, hv, lv);
    __syncthreads();

    float acc[2][8][4];
    #pragma unroll
    for (int mf = 0; mf < 2; mf++)
        #pragma unroll
        for (int nf = 0; nf < 8; nf++)
            #pragma unroll
            for (int v = 0; v < 4; v++) acc[mf][nf][v] = 0.f;

    float m1[4], m2[4]; int i1[4];
    #pragma unroll
    for (int k = 0; k < 4; k++) { m1[k] = 3.4e38f; m2[k] = 3.4e38f; i1[k] = 0; }

    const uint32_t laneOff = (uint32_t)lane * 16;
    const uint32_t q4 = (uint32_t)(lane & 3) * 4;
    const int nbase = wn * 64 + (lane >> 2);

    for (int g = 0; g < GLOBS; g++) {
        if (g + 1 < GLOBS) ldgB(g + 1, tid, hv, lv);

        char* bb = smem + B_BASE + (g & 1) * B_BUF_SZ;
        const int kc = g & 3;
        #pragma unroll
        for (int sp = 0; sp < 4; sp++) {
            int sg = kc * 4 + sp;
            uint4 ah[2], al[2];
            #pragma unroll
            for (int mf = 0; mf < 2; mf++) {
                uint32_t aoff = (uint32_t)(((wm * 2 + mf) * 16 + sg) * 512) + laneOff;
                ah[mf] = *(const uint4*)(smem + aoff);
                al[mf] = *(const uint4*)(smem + A_LO_OFF + aoff);
            }
            #pragma unroll
            for (int nf = 0; nf < 8; nf++) {
                uint32_t boff = (uint32_t)((nbase + nf * 8) * B_STRIDE + sp * 32) + q4;
                uint32_t bh0 = *(const uint32_t*)(bb + boff);
                uint32_t bh1 = *(const uint32_t*)(bb + boff + 16);
                uint32_t bl0 = *(const uint32_t*)(bb + B_LO_OFF + boff);
                uint32_t bl1 = *(const uint32_t*)(bb + B_LO_OFF + boff + 16);
                #pragma unroll
                for (int mf = 0; mf < 2; mf++) {
                    mma_bf16(acc[mf][nf], ah[mf], bh0, bh1);
                    mma_bf16(acc[mf][nf], ah[mf], bl0, bl1);
                    mma_bf16(acc[mf][nf], al[mf], bh0, bh1);
                }
            }
        }
        __syncthreads();
        if (g + 1 < GLOBS) stsB(smem, g + 1, tid, hv, lv);

        if (kc == 3) {
            // epilogue for tile t = g>>2 (codes ascending within thread)
            int cb = (g >> 2) * NTILE + wn * 64;
            #pragma unroll
            for (int nf = 0; nf < 8; nf++) {
                int c0 = cb + nf * 8 + (lane & 3) * 2;
                float w2a = __ldg(&g_w2[c0]);
                float w2b = __ldg(&g_w2[c0 + 1]);
                #pragma unroll
                for (int mf = 0; mf < 2; mf++) {
                    float d00 = fmaf(-2.f, acc[mf][nf][0], w2a);
                    float d01 = fmaf(-2.f, acc[mf][nf][1], w2b);
                    float d10 = fmaf(-2.f, acc[mf][nf][2], w2a);
                    float d11 = fmaf(-2.f, acc[mf][nf][3], w2b);
                    int k0 = mf * 2, k1 = mf * 2 + 1;
                    if (d00 < m1[k0]) { m2[k0] = m1[k0]; m1[k0] = d00; i1[k0] = c0; }
                    else if (d00 < m2[k0]) m2[k0] = d00;
                    if (d01 < m1[k0]) { m2[k0] = m1[k0]; m1[k0] = d01; i1[k0] = c0 + 1; }
                    else if (d01 < m2[k0]) m2[k0] = d01;
                    if (d10 < m1[k1]) { m2[k1] = m1[k1]; m1[k1] = d10; i1[k1] = c0; }
                    else if (d10 < m2[k1]) m2[k1] = d10;
                    if (d11 < m1[k1]) { m2[k1] = m1[k1]; m1[k1] = d11; i1[k1] = c0 + 1; }
                    else if (d11 < m2[k1]) m2[k1] = d11;
                    acc[mf][nf][0] = 0.f; acc[mf][nf][1] = 0.f;
                    acc[mf][nf][2] = 0.f; acc[mf][nf][3] = 0.f;
                }
            }
        }
        __syncthreads();
    }

    // quad reduce (lanes q=0..3 hold disjoint code sets for the same rows)
    #pragma unroll
    for (int k = 0; k < 4; k++) {
        #pragma unroll
        for (int off = 1; off <= 2; off <<= 1) {
            float o1 = __shfl_xor_sync(0xffffffffu, m1[k], off);
            float o2 = __shfl_xor_sync(0xffffffffu, m2[k], off);
            int   oi = __shfl_xor_sync(0xffffffffu, i1[k], off);
            MERGE(m1[k], m2[k], i1[k], o1, o2, oi);
        }
    }

    float* red1 = (float*)smem;           // reuse A region (all compute done)
    float* red2 = (float*)(smem + 1024);
    int*   redi = (int*)(smem + 2048);
    if ((lane & 3) == 0) {
        #pragma unroll
        for (int k = 0; k < 4; k++) {
            int rl = wm * 32 + (k >> 1) * 16 + (lane >> 2) + (k & 1) * 8;
            red1[rl * 2 + wn] = m1[k];
            red2[rl * 2 + wn] = m2[k];
            redi[rl * 2 + wn] = i1[k];
        }
    }
    __syncthreads();
    if (tid < 128) {
        float a1 = red1[tid * 2], a2 = red2[tid * 2]; int ai = redi[tid * 2];
        float b1 = red1[tid * 2 + 1], b2 = red2[tid * 2 + 1]; int bi = redi[tid * 2 + 1];
        MERGE(a1, a2, ai, b1, b2, bi);
        int rowG = blockIdx.x * 128 + tid;
        g_idx[rowG] = ai;
        outIdxF[rowG] = (float)ai;
        if (a2 - a1 < MARGIN) {
            int p = atomicAdd(&g_flagCnt, 1);
            g_flagList[p] = rowG;
        }
    }
}

// ---- k2: exact fp32 fallback for flagged rows -----------------------------
__global__ void __launch_bounds__(256) fallback_kernel(
    const float* __restrict__ z, const float* __restrict__ w,
    float* __restrict__ outIdxF)
{
    __shared__ float zr[EDIM];
    __shared__ float wv[8]; __shared__ int wi[8];
    int nflag = g_flagCnt;
    int wid = threadIdx.x >> 5, lane = threadIdx.x & 31;
    for (int f = blockIdx.x; f < nflag; f += gridDim.x) {
        int rowG = g_flagList[f];
        int b = rowG >> 12, s = rowG & 4095;
        zr[threadIdx.x] = z[(size_t)b * (EDIM * SPB) + (size_t)threadIdx.x * SPB + s];
        __syncthreads();
        float bv = 3.4e38f; int bi = 0;
        const float* zz = zr + lane * 8;
        for (int c = wid; c < NE; c += 8) {
            const float4* wr4 = (const float4*)(w + (size_t)c * EDIM + lane * 8);
            float4 p0 = wr4[0], p1 = wr4[1];
            float dot = 0.f;
            dot = fmaf(p0.x, zz[0], dot); dot = fmaf(p0.y, zz[1], dot);
            dot = fmaf(p0.z, zz[2], dot); dot = fmaf(p0.w, zz[3], dot);
            dot = fmaf(p1.x, zz[4], dot); dot = fmaf(p1.y, zz[5], dot);
            dot = fmaf(p1.z, zz[6], dot); dot = fmaf(p1.w, zz[7], dot);
            #pragma unroll
            for (int o = 16; o > 0; o >>= 1) dot += __shfl_xor_sync(0xffffffffu, dot, o);
            float d = fmaf(-2.f, dot, __ldg(&g_w2[c]));
            if (d < bv) { bv = d; bi = c; }
        }
        if (lane == 0) { wv[wid] = bv; wi[wid] = bi; }
        __syncthreads();
        if (threadIdx.x == 0) {
            float m = wv[0]; int mi = wi[0];
            #pragma unroll
            for (int q = 1; q < 8; q++)
                if (wv[q] < m || (wv[q] == m && wi[q] < mi)) { m = wv[q]; mi = wi[q]; }
            g_idx[rowG] = mi;
            outIdxF[rowG] = (float)mi;
        }
        __syncthreads();
    }
}

// ---- k3: gather z_q + loss partials + histogram ---------------------------
__global__ void gather_kernel(const float* __restrict__ z,
                              const float* __restrict__ w,
                              float* __restrict__ out)
{
    __shared__ int   sIdx[64];
    __shared__ float red[256];
    int t = threadIdx.x;
    int tile = blockIdx.x;
    int b = tile >> 6, s0 = (tile & 63) << 6;
    if (t < 64) {
        sIdx[t] = g_idx[b * SPB + s0 + t];
        atomicAdd(&g_counts[sIdx[t]], 1);
    }
    __syncthreads();
    int sL = t & 63, cg = t >> 6;
    size_t base = (size_t)b * (EDIM * SPB) + s0 + sL;
    const float* wrow = w + (size_t)sIdx[sL] * EDIM;
    float acc = 0.f;
    for (int c = cg; c < EDIM; c += 4) {
        float wq = __ldg(&wrow[c]);
        float zv = z[base + (size_t)c * SPB];
        out[base + (size_t)c * SPB] = zv + (wq - zv);
        float df = wq - zv;
        acc = fmaf(df, df, acc);
    }
    red[t] = acc;
    __syncthreads();
    for (int o = 128; o > 0; o >>= 1) {
        if (t < o) red[t] += red[t + o];
        __syncthreads();
    }
    if (t == 0) g_lossPart[tile] = red[0];
}

// ---- k4: scalars ----------------------------------------------------------
__global__ void finalize_kernel(float* __restrict__ outScal) {
    __shared__ float sp[256]; __shared__ float sl[256]; __shared__ int su[256];
    int t = threadIdx.x;
    float pl = 0.f; int un = 0;
    for (int e = t; e < NE; e += 256) {
        int cnt = g_counts[e];
        if (cnt > 0) {
            un++;
            float p = (float)cnt * (1.f / 16384.f);
            pl = fmaf(p, logf(p + 1e-10f), pl);
        }
    }
    sp[t] = pl; su[t] = un; sl[t] = g_lossPart[t];
    __syncthreads();
    for (int o = 128; o > 0; o >>= 1) {
        if (t < o) { sp[t] += sp[t + o]; su[t] += su[t + o]; sl[t] += sl[t + o]; }
        __syncthreads();
    }
    if (t == 0) {
        outScal[0] = 0.25f * sl[0] * (1.f / 4194304.f);
        outScal[1] = expf(-sp[0]);
        outScal[2] = (float)su[0];
    }
}

// ---------------------------------------------------------------------------
extern "C" void kernel_launch(void* const* d_in, const int* in_sizes, int n_in,
                              void* d_out, int out_size)
{
    const float* z = (const float*)d_in[0];
    const float* w = (const float*)d_in[1];
    float* out = (float*)d_out;
    int idxOff = out_size - N_ROWS;

    cudaFuncSetAttribute(argmin_hmma_kernel,
                         cudaFuncAttributeMaxDynamicSharedMemorySize, SM_TOTAL);

    prep_kernel<<<1024, 256>>>(w);
    argmin_hmma_kernel<<<128, 256, SM_TOTAL>>>(z, out + idxOff);
    fallback_kernel<<<128, 256>>>(z, w, out + idxOff);
    gather_kernel<<<256, 256>>>(z, w, out);
    finalize_kernel<<<1, 256>>>(out + idxOff - 3);
}